// round 8
// baseline (speedup 1.0000x reference)
#include <cuda_runtime.h>
#include <cstdint>

#define NPTS   100000
#define PPROP  256
#define RFEAT  256
#define CO     21
#define NCHUNK 74
#define CHUNK  1352      // 74*1352 = 100048 >= 100000
#define CPAD   1536      // padded chunk (48 u32 mask words)
#define NWORD  48
#define TILE   32        // points per feature tile (= one mask word)
#define PG     64        // proposals per block

// Scratch (__device__ globals: allocation-free rule)
__device__ float g_partial[NCHUNK][PPROP][RFEAT];   // 19.4 MB
__device__ float g_pcounts[NCHUNK][PPROP];
__device__ float g_cls[PPROP * CO];
__device__ float g_obj[PPROP * CO];

__device__ __forceinline__ void cp16(uint32_t saddr, const void* gptr) {
    asm volatile("cp.async.cg.shared.global [%0], [%1], 16;\n"
                 :: "r"(saddr), "l"(gptr));
}
__device__ __forceinline__ void cp_commit() {
    asm volatile("cp.async.commit_group;\n");
}
__device__ __forceinline__ void cp_wait1() {
    asm volatile("cp.async.wait_group 1;\n");
}
#define ADD_F32X2(out, a, b) \
    asm("add.rn.f32x2 %0, %1, %2;" : "=l"(out) : "l"(a), "l"(b))

struct PoolSmem {
    union {
        float4 sf[3][TILE][64];   // 96 KB feature triple-buffer
        float4 sxyz4[CPAD];       // 24 KB padded xyz (phase A only)
    } u;
    unsigned smask[PG][NWORD];    // 12 KB bitmaps
    float    scnt[8][PG];         // 2 KB
};
#define POOL_SMEM_BYTES ((int)sizeof(PoolSmem))

// ---------------------------------------------------------------------------
// Kernel 1: sparse ROI pooling.
// grid = (74 chunks, 4 proposal-groups), block = 512, 2 CTAs/SM.
// Phase A: stage chunk xyz as float4 -> full-chunk 1536-bit mask per proposal
//          (thread t: proposal t&63, points [192q, 192q+192), q = t>>6;
//          one broadcast LDS.128 per point test).
// Phase B: TRIPLE-buffered cp.async tiles (32 pts x 256 f32), ONE
//          __syncthreads per tile: issuing tile t+2 into buf (t+2)%3 reuses
//          tile t-1's buffer, already consumed by all warps before the
//          iteration-t barrier. Warp w owns proposals [4w,4w+4) and ALL 256
//          features; per membership: 2x LDS.128 + 4x packed f32x2 adds.
// ---------------------------------------------------------------------------
__global__ __launch_bounds__(512, 2)
void pool_kernel(const float* __restrict__ proposals,
                 const float* __restrict__ xyz,
                 const float* __restrict__ feats)
{
    extern __shared__ char smem_raw[];
    PoolSmem* s = reinterpret_cast<PoolSmem*>(smem_raw);

    const int chunk = blockIdx.x;
    const int pbase = blockIdx.y * PG;
    const int tid   = threadIdx.x;
    const int w     = tid >> 5;
    const int l     = tid & 31;
    const int pm    = tid & 63;   // proposal this thread masks
    const int q     = tid >> 6;   // point range [192q, 192q+192)

    const int base = chunk * CHUNK;
    const int nPts = (NPTS - base < CHUNK) ? (NPTS - base) : CHUNK;

    // ---- Phase A: stage xyz as padded float4 (pad 2.0 -> outside all boxes)
    {
        const float* gx = xyz + (size_t)base * 3;
#pragma unroll
        for (int k = 0; k < 3; k++) {               // 3*512 = 1536 = CPAD
            const int j = tid + k * 512;
            float x = 2.f, y = 2.f, z = 2.f;
            if (j < nPts) { x = gx[3*j]; y = gx[3*j+1]; z = gx[3*j+2]; }
            s->u.sxyz4[j] = make_float4(x, y, z, 0.f);
        }
    }

    // Box bounds, bit-exact vs reference (no FMA contraction).
    float alox, ahix, aloy, ahiy, aloz, ahiz;
    {
        const float* pr = proposals + (size_t)(pbase + pm) * 6;
        const float cx = pr[0], cy = pr[1], cz = pr[2];
        const float hx = __fmul_rn(pr[3], 0.5f);
        const float hy = __fmul_rn(pr[4], 0.5f);
        const float hz = __fmul_rn(pr[5], 0.5f);
        alox = __fsub_rn(cx, hx);  ahix = __fadd_rn(cx, hx);
        aloy = __fsub_rn(cy, hy);  ahiy = __fadd_rn(cy, hy);
        aloz = __fsub_rn(cz, hz);  ahiz = __fadd_rn(cz, hz);
    }
    __syncthreads();

    // ---- Build masks: 6 words of 32 tests each (one LDS.128 per test) ----
    {
        float cnt = 0.f;
#pragma unroll
        for (int wd = 0; wd < 6; wd++) {
            unsigned bits = 0;
#pragma unroll
            for (int k = 0; k < 32; k++) {
                const float4 v = s->u.sxyz4[q * 192 + wd * 32 + k];
                const bool in = (v.x >= alox) & (v.x <= ahix) &
                                (v.y >= aloy) & (v.y <= ahiy) &
                                (v.z >= aloz) & (v.z <= ahiz);
                bits |= ((unsigned)in) << k;
            }
            s->smask[pm][q * 6 + wd] = bits;
            cnt += (float)__popc(bits);
        }
        s->scnt[q][pm] = cnt;
    }
    __syncthreads();   // masks done; xyz area now reusable for features

    if (tid < PG) {
        float c = 0.f;
#pragma unroll
        for (int k = 0; k < 8; k++) c += s->scnt[k][tid];
        g_pcounts[chunk][pbase + tid] = c;
    }

    // ---- Phase B: triple-buffered pipelined accumulation ----
    ulonglong2 accA[4], accB[4];
#pragma unroll
    for (int j = 0; j < 4; j++) {
        accA[j].x = 0ull; accA[j].y = 0ull;
        accB[j].x = 0ull; accB[j].y = 0ull;
    }

    const float4* gf = reinterpret_cast<const float4*>(feats);
    const int ntiles = (nPts + TILE - 1) / TILE;

    const int ci = tid >> 6;   // base point within tile (0..7)
    const int cf = tid & 63;   // float4 column

    auto issue = [&](int t, int buf) {
        const int t0 = t * TILE;
#pragma unroll
        for (int k = 0; k < 4; k++) {
            const int i = ci + 8 * k;
            const int pt = t0 + i;
            if (pt < nPts) {
                uint32_t sa = (uint32_t)__cvta_generic_to_shared(&s->u.sf[buf][i][cf]);
                cp16(sa, gf + (size_t)(base + pt) * 64 + cf);
            }
        }
        cp_commit();
    };

    issue(0, 0);
    issue(1, 1);
    int bcur = 0, bnext = 2;   // bcur = t%3, bnext = (t+2)%3
    for (int t = 0; t < ntiles; t++) {
        cp_wait1();          // this thread's group t landed (t+1 in flight)
        __syncthreads();     // tile t visible to all; tile t-1 consumed by all

        if (t + 2 < ntiles) issue(t + 2, bnext);
        else cp_commit();    // keep group count aligned

#pragma unroll
        for (int j = 0; j < 4; j++) {
            unsigned m = s->smask[(w << 2) + j][t];
            while (m) {
                const int i = __ffs(m) - 1;
                m &= m - 1;
                const ulonglong2 va =
                    *reinterpret_cast<const ulonglong2*>(&s->u.sf[bcur][i][l]);
                const ulonglong2 vb =
                    *reinterpret_cast<const ulonglong2*>(&s->u.sf[bcur][i][l + 32]);
                ADD_F32X2(accA[j].x, accA[j].x, va.x);
                ADD_F32X2(accA[j].y, accA[j].y, va.y);
                ADD_F32X2(accB[j].x, accB[j].x, vb.x);
                ADD_F32X2(accB[j].y, accB[j].y, vb.y);
            }
        }
        bcur  = (bcur  == 2) ? 0 : bcur  + 1;
        bnext = (bnext == 2) ? 0 : bnext + 1;
    }

    // Write partial sums (coalesced 512B bursts)
#pragma unroll
    for (int j = 0; j < 4; j++) {
        const int p = (w << 2) + j;
        ulonglong2* row =
            reinterpret_cast<ulonglong2*>(&g_partial[chunk][pbase + p][0]);
        row[l]      = accA[j];
        row[l + 32] = accB[j];
    }
}

// ---------------------------------------------------------------------------
// Kernel 2: reduce partials -> roi -> logits (warp-parallel dots).
// grid = 256 (block per proposal), block = 256. Deep-MLP chunk sum.
// ---------------------------------------------------------------------------
__global__ __launch_bounds__(256)
void reduce_kernel(const float* __restrict__ W_cls, const float* __restrict__ b_cls,
                   const float* __restrict__ W_obj, const float* __restrict__ b_obj)
{
    const int p   = blockIdx.x;
    const int tid = threadIdx.x;
    const int w   = tid >> 5;
    const int l   = tid & 31;

    __shared__ float roi[RFEAT];
    __shared__ float sc[8];

    float s0 = 0.f, s1 = 0.f, s2 = 0.f, s3 = 0.f;
#pragma unroll
    for (int c = 0; c < 72; c += 4) {
        s0 += g_partial[c    ][p][tid];
        s1 += g_partial[c + 1][p][tid];
        s2 += g_partial[c + 2][p][tid];
        s3 += g_partial[c + 3][p][tid];
    }
    s0 += g_partial[72][p][tid];
    s1 += g_partial[73][p][tid];
    const float sum = (s0 + s1) + (s2 + s3);

    float cv = (tid < NCHUNK) ? g_pcounts[tid][p] : 0.f;
#pragma unroll
    for (int o = 16; o > 0; o >>= 1) cv += __shfl_down_sync(0xffffffffu, cv, o);
    if (l == 0) sc[w] = cv;
    __syncthreads();
    if (tid == 0) {
        float t = 0.f;
#pragma unroll
        for (int i = 0; i < 8; i++) t += sc[i];
        sc[0] = 1.0f / fmaxf(t, 1.0f);
    }
    __syncthreads();
    roi[tid] = sum * sc[0];
    __syncthreads();

    for (int o = w; o < 2 * CO; o += 8) {
        const bool isobj = o >= CO;
        const int  j     = isobj ? o - CO : o;
        const float* Wm  = isobj ? W_obj : W_cls;
        float a = 0.f;
#pragma unroll
        for (int f = l; f < RFEAT; f += 32) a += roi[f] * Wm[f * CO + j];
#pragma unroll
        for (int off = 16; off > 0; off >>= 1)
            a += __shfl_xor_sync(0xffffffffu, a, off);
        if (l == 0)
            (isobj ? g_obj : g_cls)[p * CO + j] = a + (isobj ? b_obj[j] : b_cls[j]);
    }
}

// ---------------------------------------------------------------------------
// Kernel 3: softmaxes + product. 1 block, 256 threads.
// ---------------------------------------------------------------------------
__global__ __launch_bounds__(256)
void softmax_kernel(float* __restrict__ out)
{
    const int tid = threadIdx.x;
    __shared__ float sobj[PPROP * CO];   // 21 KB
    __shared__ float red[CO][12];
    __shared__ float cmax[CO], cinv[CO];

    for (int e = tid; e < PPROP * CO; e += 256) sobj[e] = g_obj[e];
    __syncthreads();

    const int c = tid / 12;   // column (0..20) for tid < 252
    const int r = tid % 12;

    if (tid < 252) {
        float m = -3.4e38f;
        for (int p = r; p < PPROP; p += 12) m = fmaxf(m, sobj[p * CO + c]);
        red[c][r] = m;
    }
    __syncthreads();
    if (tid < CO) {
        float m = red[tid][0];
#pragma unroll
        for (int k = 1; k < 12; k++) m = fmaxf(m, red[tid][k]);
        cmax[tid] = m;
    }
    __syncthreads();
    if (tid < 252) {
        const float m = cmax[c];
        float sm = 0.f;
        for (int p = r; p < PPROP; p += 12) {
            const float e = expf(sobj[p * CO + c] - m);
            sobj[p * CO + c] = e;
            sm += e;
        }
        red[c][r] = sm;
    }
    __syncthreads();
    if (tid < CO) {
        float sm = 0.f;
#pragma unroll
        for (int k = 0; k < 12; k++) sm += red[tid][k];
        cinv[tid] = 1.0f / sm;
    }

    float lg[CO];
    {
        float m = -3.4e38f;
#pragma unroll
        for (int j = 0; j < CO; j++) { lg[j] = g_cls[tid * CO + j]; m = fmaxf(m, lg[j]); }
        float sm = 0.f;
#pragma unroll
        for (int j = 0; j < CO; j++) { lg[j] = expf(lg[j] - m); sm += lg[j]; }
        const float invs = 1.0f / sm;
#pragma unroll
        for (int j = 0; j < CO; j++) lg[j] *= invs;
    }
    __syncthreads();

#pragma unroll
    for (int j = 0; j < CO; j++)
        out[tid * CO + j] = lg[j] * sobj[tid * CO + j] * cinv[j];
}

// ---------------------------------------------------------------------------
extern "C" void kernel_launch(void* const* d_in, const int* in_sizes, int n_in,
                              void* d_out, int out_size)
{
    const float* proposals = (const float*)d_in[0];
    const float* input_xyz = (const float*)d_in[1];
    const float* seg_feats = (const float*)d_in[2];
    const float* W_cls     = (const float*)d_in[3];
    const float* b_cls     = (const float*)d_in[4];
    const float* W_obj     = (const float*)d_in[5];
    const float* b_obj     = (const float*)d_in[6];
    float* out = (float*)d_out;

    (void)in_sizes; (void)n_in; (void)out_size;

    cudaFuncSetAttribute(pool_kernel,
                         cudaFuncAttributeMaxDynamicSharedMemorySize,
                         POOL_SMEM_BYTES);
    pool_kernel<<<dim3(NCHUNK, 4), 512, POOL_SMEM_BYTES>>>(proposals, input_xyz, seg_feats);
    reduce_kernel<<<PPROP, 256>>>(W_cls, b_cls, W_obj, b_obj);
    softmax_kernel<<<1, 256>>>(out);
}

// round 11
// speedup vs baseline: 1.0030x; 1.0030x over previous
#include <cuda_runtime.h>
#include <cstdint>

#define NPTS   100000
#define PPROP  256
#define RFEAT  256
#define CO     21
#define NCHUNK 74
#define CHUNK  1352      // 74*1352 = 100048 >= 100000
#define CPAD   1536      // padded chunk (48 u32 mask words)
#define NWORD  48
#define TILE   32        // points per feature tile (= one mask word)
#define PG     64        // proposals per block

// Scratch (__device__ globals: allocation-free rule)
__device__ uint32_t g_partial_bf[NCHUNK][PPROP][RFEAT / 2];   // 9.7 MB bf16x2
__device__ float    g_pcounts[NCHUNK][PPROP];
__device__ float    g_cls[PPROP * CO];
__device__ float    g_obj[PPROP * CO];

__device__ __forceinline__ void cp16(uint32_t saddr, const void* gptr) {
    asm volatile("cp.async.cg.shared.global [%0], [%1], 16;\n"
                 :: "r"(saddr), "l"(gptr));
}
__device__ __forceinline__ void cp_commit() {
    asm volatile("cp.async.commit_group;\n");
}
__device__ __forceinline__ void cp_wait1() {
    asm volatile("cp.async.wait_group 1;\n");
}
#define ADD_F32X2(out, a, b) \
    asm("add.rn.f32x2 %0, %1, %2;" : "=l"(out) : "l"(a), "l"(b))

// pack f32x2 (lo = even feat, hi = odd feat) -> bf16x2 (lo16 = even feat)
static __device__ __forceinline__ uint32_t pack_bf(unsigned long long p) {
    uint32_t lo, hi, r;
    asm("mov.b64 {%0, %1}, %2;" : "=r"(lo), "=r"(hi) : "l"(p));
    asm("cvt.rn.bf16x2.f32 %0, %1, %2;" : "=r"(r)
        : "f"(__uint_as_float(hi)), "f"(__uint_as_float(lo)));
    return r;
}

struct PoolSmem {
    union {
        float4 sf[2][TILE][64];   // 64 KB feature double-buffer (f32)
        float  sxyz[CPAD * 3];    // 18 KB xyz staging (phase A only)
    } u;
    unsigned smask[PG][NWORD];    // 12 KB bitmaps
    float    scnt[8][PG];         // 2 KB
};
#define POOL_SMEM_BYTES ((int)sizeof(PoolSmem))

// ---------------------------------------------------------------------------
// Kernel 1: sparse ROI pooling (Round-6 proven structure).
// grid = (74 chunks, 4 proposal-groups), block = 512, 2 CTAs/SM.
// Phase A: stage chunk xyz -> full-chunk 1536-bit mask per proposal.
// Phase B: double-buffered cp.async tiles (32 pts x 256 f32 feats);
//          warp w owns proposals [4w, 4w+4) and ALL 256 features;
//          per membership: 2x LDS.128 + 4x packed f32x2 adds.
// Output: partial sums packed to bf16x2 (halved DRAM traffic).
// ---------------------------------------------------------------------------
__global__ __launch_bounds__(512, 2)
void pool_kernel(const float* __restrict__ proposals,
                 const float* __restrict__ xyz,
                 const float* __restrict__ feats)
{
    extern __shared__ char smem_raw[];
    PoolSmem* s = reinterpret_cast<PoolSmem*>(smem_raw);

    const int chunk = blockIdx.x;
    const int pbase = blockIdx.y * PG;
    const int tid   = threadIdx.x;
    const int w     = tid >> 5;
    const int l     = tid & 31;
    const int pm    = tid & 63;   // proposal this thread masks
    const int q     = tid >> 6;   // point range [192q, 192q+192)

    const int base = chunk * CHUNK;
    const int nPts = (NPTS - base < CHUNK) ? (NPTS - base) : CHUNK;

    // ---- Phase A: stage xyz (pad with 2.0 -> outside all boxes) ----
    {
        const float* gx = xyz + (size_t)base * 3;
        const int nf = nPts * 3;
#pragma unroll
        for (int k = 0; k < 9; k++) {               // 9*512 = 4608 = CPAD*3
            const int j = tid + k * 512;
            s->u.sxyz[j] = (j < nf) ? gx[j] : 2.0f;
        }
    }

    // Box bounds, bit-exact vs reference (no FMA contraction).
    float alox, ahix, aloy, ahiy, aloz, ahiz;
    {
        const float* pr = proposals + (size_t)(pbase + pm) * 6;
        const float cx = pr[0], cy = pr[1], cz = pr[2];
        const float hx = __fmul_rn(pr[3], 0.5f);
        const float hy = __fmul_rn(pr[4], 0.5f);
        const float hz = __fmul_rn(pr[5], 0.5f);
        alox = __fsub_rn(cx, hx);  ahix = __fadd_rn(cx, hx);
        aloy = __fsub_rn(cy, hy);  ahiy = __fadd_rn(cy, hy);
        aloz = __fsub_rn(cz, hz);  ahiz = __fadd_rn(cz, hz);
    }
    __syncthreads();

    // ---- Build masks: 6 words of 32 tests each ----
    {
        float cnt = 0.f;
#pragma unroll
        for (int wd = 0; wd < 6; wd++) {
            unsigned bits = 0;
#pragma unroll
            for (int k = 0; k < 32; k++) {
                const int i = q * 192 + wd * 32 + k;
                const float x = s->u.sxyz[3 * i];
                const float y = s->u.sxyz[3 * i + 1];
                const float z = s->u.sxyz[3 * i + 2];
                const bool in = (x >= alox) & (x <= ahix) &
                                (y >= aloy) & (y <= ahiy) &
                                (z >= aloz) & (z <= ahiz);
                bits |= ((unsigned)in) << k;
            }
            s->smask[pm][q * 6 + wd] = bits;
            cnt += (float)__popc(bits);
        }
        s->scnt[q][pm] = cnt;
    }
    __syncthreads();   // masks done; xyz area now reusable for features

    if (tid < PG) {
        float c = 0.f;
#pragma unroll
        for (int k = 0; k < 8; k++) c += s->scnt[k][tid];
        g_pcounts[chunk][pbase + tid] = c;
    }

    // ---- Phase B: double-buffered pipelined accumulation ----
    ulonglong2 accA[4], accB[4];
#pragma unroll
    for (int j = 0; j < 4; j++) {
        accA[j].x = 0ull; accA[j].y = 0ull;
        accB[j].x = 0ull; accB[j].y = 0ull;
    }

    const float4* gf = reinterpret_cast<const float4*>(feats);
    const int ntiles = (nPts + TILE - 1) / TILE;

    const int ci = tid >> 6;   // base point within tile (0..7)
    const int cf = tid & 63;   // float4 column

    auto issue = [&](int t, int buf) {
        const int t0 = t * TILE;
#pragma unroll
        for (int k = 0; k < 4; k++) {
            const int i = ci + 8 * k;
            const int pt = t0 + i;
            if (pt < nPts) {
                uint32_t sa = (uint32_t)__cvta_generic_to_shared(&s->u.sf[buf][i][cf]);
                cp16(sa, gf + (size_t)(base + pt) * 64 + cf);
            }
        }
        cp_commit();
    };

    issue(0, 0);
    for (int t = 0; t < ntiles; t++) {
        if (t + 1 < ntiles) issue(t + 1, (t + 1) & 1);
        else cp_commit();   // keep group count aligned
        cp_wait1();
        __syncthreads();    // buf t&1 visible to all

        const int buf = t & 1;
#pragma unroll
        for (int j = 0; j < 4; j++) {
            unsigned m = s->smask[(w << 2) + j][t];
            while (m) {
                const int i = __ffs(m) - 1;
                m &= m - 1;
                const ulonglong2 va =
                    *reinterpret_cast<const ulonglong2*>(&s->u.sf[buf][i][l]);
                const ulonglong2 vb =
                    *reinterpret_cast<const ulonglong2*>(&s->u.sf[buf][i][l + 32]);
                ADD_F32X2(accA[j].x, accA[j].x, va.x);
                ADD_F32X2(accA[j].y, accA[j].y, va.y);
                ADD_F32X2(accB[j].x, accB[j].x, vb.x);
                ADD_F32X2(accB[j].y, accB[j].y, vb.y);
            }
        }
        __syncthreads();    // all consumed before buf is overwritten (t+2)
    }

    // Write partial sums as bf16x2 (coalesced 256B bursts per half-row)
#pragma unroll
    for (int j = 0; j < 4; j++) {
        const int p = (w << 2) + j;
        uint32_t* row = &g_partial_bf[chunk][pbase + p][0];
        // lane l: feats [4l,4l+4) -> u32 indices [2l, 2l+1]
        reinterpret_cast<uint2*>(row)[l] =
            make_uint2(pack_bf(accA[j].x), pack_bf(accA[j].y));
        // feats [128+4l, 128+4l+4) -> u32 indices [64+2l, 64+2l+1]
        reinterpret_cast<uint2*>(row + 64)[l] =
            make_uint2(pack_bf(accB[j].x), pack_bf(accB[j].y));
    }
}

// ---------------------------------------------------------------------------
// Kernel 2: reduce bf16 partials -> roi -> logits (warp-parallel dots).
// grid = 256 (block per proposal), block = 256.
// ---------------------------------------------------------------------------
__global__ __launch_bounds__(256)
void reduce_kernel(const float* __restrict__ W_cls, const float* __restrict__ b_cls,
                   const float* __restrict__ W_obj, const float* __restrict__ b_obj)
{
    const int p   = blockIdx.x;
    const int tid = threadIdx.x;
    const int w   = tid >> 5;
    const int l   = tid & 31;

    __shared__ float roi[RFEAT];
    __shared__ float sc[8];

    // Feature sums: thread t < 128 owns u32 column t (feats 2t, 2t+1).
    float e0 = 0.f, o0 = 0.f, e1 = 0.f, o1 = 0.f;
    if (tid < 128) {
        const uint32_t* colp = &g_partial_bf[0][p][tid];
        const size_t stride = (size_t)PPROP * (RFEAT / 2);
#pragma unroll
        for (int c = 0; c < NCHUNK; c += 2) {
            const uint32_t ua = colp[(size_t)c * stride];
            const uint32_t ub = colp[(size_t)(c + 1) * stride];
            e0 += __uint_as_float(ua << 16);
            o0 += __uint_as_float(ua & 0xFFFF0000u);
            e1 += __uint_as_float(ub << 16);
            o1 += __uint_as_float(ub & 0xFFFF0000u);
        }
    }

    // Count reduction
    float cv = (tid < NCHUNK) ? g_pcounts[tid][p] : 0.f;
#pragma unroll
    for (int o = 16; o > 0; o >>= 1) cv += __shfl_down_sync(0xffffffffu, cv, o);
    if (l == 0) sc[w] = cv;
    __syncthreads();
    if (tid == 0) {
        float t = 0.f;
#pragma unroll
        for (int i = 0; i < 8; i++) t += sc[i];
        sc[0] = 1.0f / fmaxf(t, 1.0f);
    }
    __syncthreads();
    if (tid < 128) {
        roi[2 * tid]     = (e0 + e1) * sc[0];
        roi[2 * tid + 1] = (o0 + o1) * sc[0];
    }
    __syncthreads();

    // Logits: 42 warp-reduced dot products of length 256
    for (int o = w; o < 2 * CO; o += 8) {
        const bool isobj = o >= CO;
        const int  j     = isobj ? o - CO : o;
        const float* Wm  = isobj ? W_obj : W_cls;
        float a = 0.f;
#pragma unroll
        for (int f = l; f < RFEAT; f += 32) a += roi[f] * Wm[f * CO + j];
#pragma unroll
        for (int off = 16; off > 0; off >>= 1)
            a += __shfl_xor_sync(0xffffffffu, a, off);
        if (l == 0)
            (isobj ? g_obj : g_cls)[p * CO + j] = a + (isobj ? b_obj[j] : b_cls[j]);
    }
}

// ---------------------------------------------------------------------------
// Kernel 3: softmaxes + product. 1 block, 256 threads.
// ---------------------------------------------------------------------------
__global__ __launch_bounds__(256)
void softmax_kernel(float* __restrict__ out)
{
    const int tid = threadIdx.x;
    __shared__ float sobj[PPROP * CO];   // 21 KB
    __shared__ float red[CO][12];
    __shared__ float cmax[CO], cinv[CO];

    for (int e = tid; e < PPROP * CO; e += 256) sobj[e] = g_obj[e];
    __syncthreads();

    const int c = tid / 12;   // column (0..20) for tid < 252
    const int r = tid % 12;

    if (tid < 252) {
        float m = -3.4e38f;
        for (int p = r; p < PPROP; p += 12) m = fmaxf(m, sobj[p * CO + c]);
        red[c][r] = m;
    }
    __syncthreads();
    if (tid < CO) {
        float m = red[tid][0];
#pragma unroll
        for (int k = 1; k < 12; k++) m = fmaxf(m, red[tid][k]);
        cmax[tid] = m;
    }
    __syncthreads();
    if (tid < 252) {
        const float m = cmax[c];
        float sm = 0.f;
        for (int p = r; p < PPROP; p += 12) {
            const float e = expf(sobj[p * CO + c] - m);
            sobj[p * CO + c] = e;
            sm += e;
        }
        red[c][r] = sm;
    }
    __syncthreads();
    if (tid < CO) {
        float sm = 0.f;
#pragma unroll
        for (int k = 0; k < 12; k++) sm += red[tid][k];
        cinv[tid] = 1.0f / sm;
    }

    float lg[CO];
    {
        float m = -3.4e38f;
#pragma unroll
        for (int j = 0; j < CO; j++) { lg[j] = g_cls[tid * CO + j]; m = fmaxf(m, lg[j]); }
        float sm = 0.f;
#pragma unroll
        for (int j = 0; j < CO; j++) { lg[j] = expf(lg[j] - m); sm += lg[j]; }
        const float invs = 1.0f / sm;
#pragma unroll
        for (int j = 0; j < CO; j++) lg[j] *= invs;
    }
    __syncthreads();

#pragma unroll
    for (int j = 0; j < CO; j++)
        out[tid * CO + j] = lg[j] * sobj[tid * CO + j] * cinv[j];
}

// ---------------------------------------------------------------------------
extern "C" void kernel_launch(void* const* d_in, const int* in_sizes, int n_in,
                              void* d_out, int out_size)
{
    const float* proposals = (const float*)d_in[0];
    const float* input_xyz = (const float*)d_in[1];
    const float* seg_feats = (const float*)d_in[2];
    const float* W_cls     = (const float*)d_in[3];
    const float* b_cls     = (const float*)d_in[4];
    const float* W_obj     = (const float*)d_in[5];
    const float* b_obj     = (const float*)d_in[6];
    float* out = (float*)d_out;

    (void)in_sizes; (void)n_in; (void)out_size;

    cudaFuncSetAttribute(pool_kernel,
                         cudaFuncAttributeMaxDynamicSharedMemorySize,
                         POOL_SMEM_BYTES);
    pool_kernel<<<dim3(NCHUNK, 4), 512, POOL_SMEM_BYTES>>>(proposals, input_xyz, seg_feats);
    reduce_kernel<<<PPROP, 256>>>(W_cls, b_cls, W_obj, b_obj);
    softmax_kernel<<<1, 256>>>(out);
}

// round 12
// speedup vs baseline: 1.0215x; 1.0185x over previous
#include <cuda_runtime.h>
#include <cstdint>

#define NPTS   100000
#define PPROP  256
#define RFEAT  256
#define CO     21
#define NCHUNK 74
#define CHUNK  1352      // 74*1352 = 100048 >= 100000
#define CPAD   1536      // padded chunk (48 u32 mask words)
#define NWORD  48
#define TILE   32        // points per feature tile (= one mask word)
#define PG     64        // proposals per block

// Scratch (__device__ globals: allocation-free rule)
__device__ uint32_t g_partial_bf[NCHUNK][PPROP][RFEAT / 2];   // 9.7 MB bf16x2
__device__ float    g_pcounts[NCHUNK][PPROP];
__device__ float    g_cls[PPROP * CO];
__device__ float    g_obj[PPROP * CO];

__device__ __forceinline__ void cp16(uint32_t saddr, const void* gptr) {
    asm volatile("cp.async.cg.shared.global [%0], [%1], 16;\n"
                 :: "r"(saddr), "l"(gptr));
}
__device__ __forceinline__ void cp_commit() {
    asm volatile("cp.async.commit_group;\n");
}
__device__ __forceinline__ void cp_wait1() {
    asm volatile("cp.async.wait_group 1;\n");
}
#define ADD_F32X2(out, a, b) \
    asm("add.rn.f32x2 %0, %1, %2;" : "=l"(out) : "l"(a), "l"(b))

// pack f32x2 (lo = even feat, hi = odd feat) -> bf16x2 (lo16 = even feat)
static __device__ __forceinline__ uint32_t pack_bf(unsigned long long p) {
    uint32_t lo, hi, r;
    asm("mov.b64 {%0, %1}, %2;" : "=r"(lo), "=r"(hi) : "l"(p));
    asm("cvt.rn.bf16x2.f32 %0, %1, %2;" : "=r"(r)
        : "f"(__uint_as_float(hi)), "f"(__uint_as_float(lo)));
    return r;
}

struct PoolSmem {
    union {
        float4 sf[2][TILE][64];   // 64 KB feature double-buffer (f32)
        float4 sxyz4[CPAD];       // 24 KB padded xyz (phase A only)
    } u;
    unsigned smaskT[NWORD][PG];   // 12 KB bitmaps, word-major (transposed)
    float    scnt[8][PG];         // 2 KB
};
#define POOL_SMEM_BYTES ((int)sizeof(PoolSmem))

// ---------------------------------------------------------------------------
// Kernel 1: sparse ROI pooling.
// grid = (74 chunks, 4 proposal-groups), block = 512, 2 CTAs/SM.
// Phase A: stage chunk xyz as float4 -> full-chunk bitmaps, word-major:
//          smaskT[word][prop]; one broadcast LDS.128 per point test.
// Phase B: double-buffered cp.async tiles (32 pts x 256 f32 feats);
//          warp w owns proposals [4w, 4w+4): fetches their 4 mask words for
//          tile t with ONE broadcast LDS.128, scans each; per membership:
//          2x LDS.128 + 4x packed f32x2 adds into register accumulators.
// Output: partial sums packed to bf16x2 (halved DRAM traffic).
// ---------------------------------------------------------------------------
__global__ __launch_bounds__(512, 2)
void pool_kernel(const float* __restrict__ proposals,
                 const float* __restrict__ xyz,
                 const float* __restrict__ feats)
{
    extern __shared__ char smem_raw[];
    PoolSmem* s = reinterpret_cast<PoolSmem*>(smem_raw);

    const int chunk = blockIdx.x;
    const int pbase = blockIdx.y * PG;
    const int tid   = threadIdx.x;
    const int w     = tid >> 5;
    const int l     = tid & 31;
    const int pm    = tid & 63;   // proposal this thread masks
    const int q     = tid >> 6;   // point range [192q, 192q+192)

    const int base = chunk * CHUNK;
    const int nPts = (NPTS - base < CHUNK) ? (NPTS - base) : CHUNK;

    // ---- Phase A: stage xyz as padded float4 (pad 2.0 -> outside all boxes)
    {
        const float* gx = xyz + (size_t)base * 3;
#pragma unroll
        for (int k = 0; k < 3; k++) {               // 3*512 = 1536 = CPAD
            const int j = tid + k * 512;
            float x = 2.f, y = 2.f, z = 2.f;
            if (j < nPts) { x = gx[3*j]; y = gx[3*j+1]; z = gx[3*j+2]; }
            s->u.sxyz4[j] = make_float4(x, y, z, 0.f);
        }
    }

    // Box bounds, bit-exact vs reference (no FMA contraction).
    float alox, ahix, aloy, ahiy, aloz, ahiz;
    {
        const float* pr = proposals + (size_t)(pbase + pm) * 6;
        const float cx = pr[0], cy = pr[1], cz = pr[2];
        const float hx = __fmul_rn(pr[3], 0.5f);
        const float hy = __fmul_rn(pr[4], 0.5f);
        const float hz = __fmul_rn(pr[5], 0.5f);
        alox = __fsub_rn(cx, hx);  ahix = __fadd_rn(cx, hx);
        aloy = __fsub_rn(cy, hy);  ahiy = __fadd_rn(cy, hy);
        aloz = __fsub_rn(cz, hz);  ahiz = __fadd_rn(cz, hz);
    }
    __syncthreads();

    // ---- Build masks: 6 words of 32 tests each (1 LDS.128 per test) ----
    {
        float cnt = 0.f;
#pragma unroll
        for (int wd = 0; wd < 6; wd++) {
            unsigned bits = 0;
#pragma unroll
            for (int k = 0; k < 32; k++) {
                const float4 v = s->u.sxyz4[q * 192 + wd * 32 + k];
                const bool in = (v.x >= alox) & (v.x <= ahix) &
                                (v.y >= aloy) & (v.y <= ahiy) &
                                (v.z >= aloz) & (v.z <= ahiz);
                bits |= ((unsigned)in) << k;
            }
            s->smaskT[q * 6 + wd][pm] = bits;
            cnt += (float)__popc(bits);
        }
        s->scnt[q][pm] = cnt;
    }
    __syncthreads();   // masks done; xyz area now reusable for features

    if (tid < PG) {
        float c = 0.f;
#pragma unroll
        for (int k = 0; k < 8; k++) c += s->scnt[k][tid];
        g_pcounts[chunk][pbase + tid] = c;
    }

    // ---- Phase B: double-buffered pipelined accumulation ----
    ulonglong2 accA[4], accB[4];
#pragma unroll
    for (int j = 0; j < 4; j++) {
        accA[j].x = 0ull; accA[j].y = 0ull;
        accB[j].x = 0ull; accB[j].y = 0ull;
    }

    const float4* gf = reinterpret_cast<const float4*>(feats);
    const int ntiles = (nPts + TILE - 1) / TILE;

    const int ci = tid >> 6;   // base point within tile (0..7)
    const int cf = tid & 63;   // float4 column

    auto issue = [&](int t, int buf) {
        const int t0 = t * TILE;
#pragma unroll
        for (int k = 0; k < 4; k++) {
            const int i = ci + 8 * k;
            const int pt = t0 + i;
            if (pt < nPts) {
                uint32_t sa = (uint32_t)__cvta_generic_to_shared(&s->u.sf[buf][i][cf]);
                cp16(sa, gf + (size_t)(base + pt) * 64 + cf);
            }
        }
        cp_commit();
    };

    issue(0, 0);
    for (int t = 0; t < ntiles; t++) {
        if (t + 1 < ntiles) issue(t + 1, (t + 1) & 1);
        else cp_commit();   // keep group count aligned
        cp_wait1();
        __syncthreads();    // buf t&1 visible to all

        const int buf = t & 1;
        // One broadcast LDS.128: mask words of proposals 4w..4w+3 for tile t
        const uint4 mw = *reinterpret_cast<const uint4*>(&s->smaskT[t][w << 2]);

#define SCAN_ONE(MWORD, J)                                                    \
        {                                                                     \
            unsigned m = (MWORD);                                             \
            while (m) {                                                       \
                const int i = __ffs(m) - 1;                                   \
                m &= m - 1;                                                   \
                const ulonglong2 va =                                         \
                    *reinterpret_cast<const ulonglong2*>(&s->u.sf[buf][i][l]);\
                const ulonglong2 vb =                                         \
                    *reinterpret_cast<const ulonglong2*>(&s->u.sf[buf][i][l + 32]);\
                ADD_F32X2(accA[J].x, accA[J].x, va.x);                        \
                ADD_F32X2(accA[J].y, accA[J].y, va.y);                        \
                ADD_F32X2(accB[J].x, accB[J].x, vb.x);                        \
                ADD_F32X2(accB[J].y, accB[J].y, vb.y);                        \
            }                                                                 \
        }
        SCAN_ONE(mw.x, 0)
        SCAN_ONE(mw.y, 1)
        SCAN_ONE(mw.z, 2)
        SCAN_ONE(mw.w, 3)
#undef SCAN_ONE

        __syncthreads();    // all consumed before buf is overwritten (t+2)
    }

    // Write partial sums as bf16x2 (coalesced 256B bursts per half-row)
#pragma unroll
    for (int j = 0; j < 4; j++) {
        const int p = (w << 2) + j;
        uint32_t* row = &g_partial_bf[chunk][pbase + p][0];
        reinterpret_cast<uint2*>(row)[l] =
            make_uint2(pack_bf(accA[j].x), pack_bf(accA[j].y));
        reinterpret_cast<uint2*>(row + 64)[l] =
            make_uint2(pack_bf(accB[j].x), pack_bf(accB[j].y));
    }
}

// ---------------------------------------------------------------------------
// Kernel 2: reduce bf16 partials -> roi -> logits (warp-parallel dots).
// grid = 256 (block per proposal), block = 256.
// ---------------------------------------------------------------------------
__global__ __launch_bounds__(256)
void reduce_kernel(const float* __restrict__ W_cls, const float* __restrict__ b_cls,
                   const float* __restrict__ W_obj, const float* __restrict__ b_obj)
{
    const int p   = blockIdx.x;
    const int tid = threadIdx.x;
    const int w   = tid >> 5;
    const int l   = tid & 31;

    __shared__ float roi[RFEAT];
    __shared__ float sc[8];

    // Feature sums: thread t < 128 owns u32 column t (feats 2t, 2t+1).
    float e0 = 0.f, o0 = 0.f, e1 = 0.f, o1 = 0.f;
    if (tid < 128) {
        const uint32_t* colp = &g_partial_bf[0][p][tid];
        const size_t stride = (size_t)PPROP * (RFEAT / 2);
#pragma unroll
        for (int c = 0; c < NCHUNK; c += 2) {
            const uint32_t ua = colp[(size_t)c * stride];
            const uint32_t ub = colp[(size_t)(c + 1) * stride];
            e0 += __uint_as_float(ua << 16);
            o0 += __uint_as_float(ua & 0xFFFF0000u);
            e1 += __uint_as_float(ub << 16);
            o1 += __uint_as_float(ub & 0xFFFF0000u);
        }
    }

    // Count reduction
    float cv = (tid < NCHUNK) ? g_pcounts[tid][p] : 0.f;
#pragma unroll
    for (int o = 16; o > 0; o >>= 1) cv += __shfl_down_sync(0xffffffffu, cv, o);
    if (l == 0) sc[w] = cv;
    __syncthreads();
    if (tid == 0) {
        float t = 0.f;
#pragma unroll
        for (int i = 0; i < 8; i++) t += sc[i];
        sc[0] = 1.0f / fmaxf(t, 1.0f);
    }
    __syncthreads();
    if (tid < 128) {
        roi[2 * tid]     = (e0 + e1) * sc[0];
        roi[2 * tid + 1] = (o0 + o1) * sc[0];
    }
    __syncthreads();

    // Logits: 42 warp-reduced dot products of length 256
    for (int o = w; o < 2 * CO; o += 8) {
        const bool isobj = o >= CO;
        const int  j     = isobj ? o - CO : o;
        const float* Wm  = isobj ? W_obj : W_cls;
        float a = 0.f;
#pragma unroll
        for (int f = l; f < RFEAT; f += 32) a += roi[f] * Wm[f * CO + j];
#pragma unroll
        for (int off = 16; off > 0; off >>= 1)
            a += __shfl_xor_sync(0xffffffffu, a, off);
        if (l == 0)
            (isobj ? g_obj : g_cls)[p * CO + j] = a + (isobj ? b_obj[j] : b_cls[j]);
    }
}

// ---------------------------------------------------------------------------
// Kernel 3: softmaxes + product. 1 block, 1024 threads.
// obj column stats: 48 threads per column.
// ---------------------------------------------------------------------------
__global__ __launch_bounds__(1024)
void softmax_kernel(float* __restrict__ out)
{
    const int tid = threadIdx.x;
    __shared__ float sobj[PPROP * CO];   // 21 KB
    __shared__ float red[CO][48];
    __shared__ float cmax[CO], cinv[CO];

    for (int e = tid; e < PPROP * CO; e += 1024) sobj[e] = g_obj[e];
    __syncthreads();

    const int c = tid / 48;   // column (0..20) for tid < 1008
    const int r = tid % 48;

    if (tid < 1008) {
        float m = -3.4e38f;
        for (int p = r; p < PPROP; p += 48) m = fmaxf(m, sobj[p * CO + c]);
        red[c][r] = m;
    }
    __syncthreads();
    if (tid < CO) {
        float m = red[tid][0];
#pragma unroll
        for (int k = 1; k < 48; k++) m = fmaxf(m, red[tid][k]);
        cmax[tid] = m;
    }
    __syncthreads();
    if (tid < 1008) {
        const float m = cmax[c];
        float sm = 0.f;
        for (int p = r; p < PPROP; p += 48) {
            const float e = expf(sobj[p * CO + c] - m);
            sobj[p * CO + c] = e;
            sm += e;
        }
        red[c][r] = sm;
    }
    __syncthreads();
    if (tid < CO) {
        float sm = 0.f;
#pragma unroll
        for (int k = 0; k < 48; k++) sm += red[tid][k];
        cinv[tid] = 1.0f / sm;
    }
    __syncthreads();

    // cls row softmax (axis=1) + product; rows split 2 ways over 512 threads
    if (tid < 512) {
        const int row  = tid >> 1;
        const int half = tid & 1;
        float lg[CO];
        float m = -3.4e38f;
#pragma unroll
        for (int j = 0; j < CO; j++) { lg[j] = g_cls[row * CO + j]; m = fmaxf(m, lg[j]); }
        float sm = 0.f;
#pragma unroll
        for (int j = 0; j < CO; j++) { lg[j] = expf(lg[j] - m); sm += lg[j]; }
        const float invs = 1.0f / sm;
        if (half == 0) {
#pragma unroll
            for (int j = 0; j < 11; j++)
                out[row * CO + j] = lg[j] * invs * sobj[row * CO + j] * cinv[j];
        } else {
#pragma unroll
            for (int j = 11; j < CO; j++)
                out[row * CO + j] = lg[j] * invs * sobj[row * CO + j] * cinv[j];
        }
    }
}

// ---------------------------------------------------------------------------
extern "C" void kernel_launch(void* const* d_in, const int* in_sizes, int n_in,
                              void* d_out, int out_size)
{
    const float* proposals = (const float*)d_in[0];
    const float* input_xyz = (const float*)d_in[1];
    const float* seg_feats = (const float*)d_in[2];
    const float* W_cls     = (const float*)d_in[3];
    const float* b_cls     = (const float*)d_in[4];
    const float* W_obj     = (const float*)d_in[5];
    const float* b_obj     = (const float*)d_in[6];
    float* out = (float*)d_out;

    (void)in_sizes; (void)n_in; (void)out_size;

    cudaFuncSetAttribute(pool_kernel,
                         cudaFuncAttributeMaxDynamicSharedMemorySize,
                         POOL_SMEM_BYTES);
    pool_kernel<<<dim3(NCHUNK, 4), 512, POOL_SMEM_BYTES>>>(proposals, input_xyz, seg_feats);
    reduce_kernel<<<PPROP, 256>>>(W_cls, b_cls, W_obj, b_obj);
    softmax_kernel<<<1, 1024>>>(out);
}

// round 13
// speedup vs baseline: 1.0242x; 1.0027x over previous
#include <cuda_runtime.h>
#include <cstdint>

#define NPTS   100000
#define PPROP  256
#define RFEAT  256
#define CO     21
#define NCHUNK 74
#define CHUNK  1352      // 74*1352 = 100048 >= 100000
#define CPAD   1536      // padded chunk (48 u32 mask words)
#define NWORD  48
#define TILE   32        // points per feature tile (= one mask word)
#define PG     64        // proposals per block

// Scratch (__device__ globals: allocation-free rule)
__device__ uint32_t g_partial_bf[NCHUNK][PPROP][RFEAT / 2];   // 9.7 MB bf16x2
__device__ float    g_pcounts[NCHUNK][PPROP];
__device__ float    g_cls[PPROP * CO];
__device__ float    g_obj[PPROP * CO];

__device__ __forceinline__ void cp16(uint32_t saddr, const void* gptr) {
    asm volatile("cp.async.cg.shared.global [%0], [%1], 16;\n"
                 :: "r"(saddr), "l"(gptr));
}
__device__ __forceinline__ void cp_commit() {
    asm volatile("cp.async.commit_group;\n");
}
__device__ __forceinline__ void cp_wait2() {
    asm volatile("cp.async.wait_group 2;\n");
}
#define ADD_F32X2(out, a, b) \
    asm("add.rn.f32x2 %0, %1, %2;" : "=l"(out) : "l"(a), "l"(b))

// pack f32x2 (lo = even feat, hi = odd feat) -> bf16x2 (lo16 = even feat)
static __device__ __forceinline__ uint32_t pack_bf(unsigned long long p) {
    uint32_t lo, hi, r;
    asm("mov.b64 {%0, %1}, %2;" : "=r"(lo), "=r"(hi) : "l"(p));
    asm("cvt.rn.bf16x2.f32 %0, %1, %2;" : "=r"(r)
        : "f"(__uint_as_float(hi)), "f"(__uint_as_float(lo)));
    return r;
}

struct PoolSmem {
    union {
        float4 sf[3][TILE][64];   // 96 KB feature triple-buffer (f32)
        float4 sxyz4[CPAD];       // 24 KB padded xyz (phase A only)
    } u;
    unsigned smaskT[NWORD][PG];   // 12 KB bitmaps, word-major (transposed)
    float    scnt[8][PG];         // 2 KB
};
#define POOL_SMEM_BYTES ((int)sizeof(PoolSmem))

// ---------------------------------------------------------------------------
// Kernel 1: sparse ROI pooling.
// grid = (74 chunks, 4 proposal-groups), block = 512, 2 CTAs/SM.
// Phase A: stage chunk xyz as float4 -> full-chunk bitmaps, word-major.
// Phase B: cp.async pipeline with PREFETCH DISTANCE 2 (3 buffers, 3 groups
//          in flight, wait_group 2): tile t+3 issued into the buffer freed
//          by the post-scan barrier of tile t. Cover ~2 iterations > DRAM
//          latency. Warp w owns proposals [4w,4w+4) and ALL 256 features;
//          per membership: 2x LDS.128 + 4x packed f32x2 adds.
// Output: partial sums packed to bf16x2 (halved DRAM traffic).
// ---------------------------------------------------------------------------
__global__ __launch_bounds__(512, 2)
void pool_kernel(const float* __restrict__ proposals,
                 const float* __restrict__ xyz,
                 const float* __restrict__ feats)
{
    extern __shared__ char smem_raw[];
    PoolSmem* s = reinterpret_cast<PoolSmem*>(smem_raw);

    const int chunk = blockIdx.x;
    const int pbase = blockIdx.y * PG;
    const int tid   = threadIdx.x;
    const int w     = tid >> 5;
    const int l     = tid & 31;
    const int pm    = tid & 63;   // proposal this thread masks
    const int q     = tid >> 6;   // point range [192q, 192q+192)

    const int base = chunk * CHUNK;
    const int nPts = (NPTS - base < CHUNK) ? (NPTS - base) : CHUNK;

    // ---- Phase A: stage xyz as padded float4 (pad 2.0 -> outside all boxes)
    {
        const float* gx = xyz + (size_t)base * 3;
#pragma unroll
        for (int k = 0; k < 3; k++) {               // 3*512 = 1536 = CPAD
            const int j = tid + k * 512;
            float x = 2.f, y = 2.f, z = 2.f;
            if (j < nPts) { x = gx[3*j]; y = gx[3*j+1]; z = gx[3*j+2]; }
            s->u.sxyz4[j] = make_float4(x, y, z, 0.f);
        }
    }

    // Box bounds, bit-exact vs reference (no FMA contraction).
    float alox, ahix, aloy, ahiy, aloz, ahiz;
    {
        const float* pr = proposals + (size_t)(pbase + pm) * 6;
        const float cx = pr[0], cy = pr[1], cz = pr[2];
        const float hx = __fmul_rn(pr[3], 0.5f);
        const float hy = __fmul_rn(pr[4], 0.5f);
        const float hz = __fmul_rn(pr[5], 0.5f);
        alox = __fsub_rn(cx, hx);  ahix = __fadd_rn(cx, hx);
        aloy = __fsub_rn(cy, hy);  ahiy = __fadd_rn(cy, hy);
        aloz = __fsub_rn(cz, hz);  ahiz = __fadd_rn(cz, hz);
    }
    __syncthreads();

    // ---- Build masks: 6 words of 32 tests each (1 LDS.128 per test) ----
    {
        float cnt = 0.f;
#pragma unroll
        for (int wd = 0; wd < 6; wd++) {
            unsigned bits = 0;
#pragma unroll
            for (int k = 0; k < 32; k++) {
                const float4 v = s->u.sxyz4[q * 192 + wd * 32 + k];
                const bool in = (v.x >= alox) & (v.x <= ahix) &
                                (v.y >= aloy) & (v.y <= ahiy) &
                                (v.z >= aloz) & (v.z <= ahiz);
                bits |= ((unsigned)in) << k;
            }
            s->smaskT[q * 6 + wd][pm] = bits;
            cnt += (float)__popc(bits);
        }
        s->scnt[q][pm] = cnt;
    }
    __syncthreads();   // masks done; xyz area now reusable for features

    if (tid < PG) {
        float c = 0.f;
#pragma unroll
        for (int k = 0; k < 8; k++) c += s->scnt[k][tid];
        g_pcounts[chunk][pbase + tid] = c;
    }

    // ---- Phase B: distance-2 pipelined accumulation ----
    ulonglong2 accA[4], accB[4];
#pragma unroll
    for (int j = 0; j < 4; j++) {
        accA[j].x = 0ull; accA[j].y = 0ull;
        accB[j].x = 0ull; accB[j].y = 0ull;
    }

    const float4* gf = reinterpret_cast<const float4*>(feats);
    const int ntiles = (nPts + TILE - 1) / TILE;

    const int ci = tid >> 6;   // base point within tile (0..7)
    const int cf = tid & 63;   // float4 column

    auto issue = [&](int t, int buf) {
        const int t0 = t * TILE;
#pragma unroll
        for (int k = 0; k < 4; k++) {
            const int i = ci + 8 * k;
            const int pt = t0 + i;
            if (pt < nPts) {
                uint32_t sa = (uint32_t)__cvta_generic_to_shared(&s->u.sf[buf][i][cf]);
                cp16(sa, gf + (size_t)(base + pt) * 64 + cf);
            }
        }
        cp_commit();
    };

    // prologue: 3 groups in flight
    issue(0, 0);
    issue(1, 1);
    issue(2, 2);

    int bcur = 0;   // t % 3
    for (int t = 0; t < ntiles; t++) {
        cp_wait2();          // tile t's group landed (t+1, t+2 in flight)
        __syncthreads();     // tile t visible to all warps

        // One broadcast LDS.128: mask words of proposals 4w..4w+3 for tile t
        const uint4 mw = *reinterpret_cast<const uint4*>(&s->smaskT[t][w << 2]);

#define SCAN_ONE(MWORD, J)                                                    \
        {                                                                     \
            unsigned m = (MWORD);                                             \
            while (m) {                                                       \
                const int i = __ffs(m) - 1;                                   \
                m &= m - 1;                                                   \
                const ulonglong2 va =                                         \
                    *reinterpret_cast<const ulonglong2*>(&s->u.sf[bcur][i][l]);\
                const ulonglong2 vb =                                         \
                    *reinterpret_cast<const ulonglong2*>(&s->u.sf[bcur][i][l + 32]);\
                ADD_F32X2(accA[J].x, accA[J].x, va.x);                        \
                ADD_F32X2(accA[J].y, accA[J].y, va.y);                        \
                ADD_F32X2(accB[J].x, accB[J].x, vb.x);                        \
                ADD_F32X2(accB[J].y, accB[J].y, vb.y);                        \
            }                                                                 \
        }
        SCAN_ONE(mw.x, 0)
        SCAN_ONE(mw.y, 1)
        SCAN_ONE(mw.z, 2)
        SCAN_ONE(mw.w, 3)
#undef SCAN_ONE

        __syncthreads();     // tile t consumed by ALL warps -> buffer free

        if (t + 3 < ntiles) issue(t + 3, bcur);   // refill freed buffer
        else cp_commit();    // keep per-thread group count aligned

        bcur = (bcur == 2) ? 0 : bcur + 1;
    }

    // Write partial sums as bf16x2 (coalesced 256B bursts per half-row)
#pragma unroll
    for (int j = 0; j < 4; j++) {
        const int p = (w << 2) + j;
        uint32_t* row = &g_partial_bf[chunk][pbase + p][0];
        reinterpret_cast<uint2*>(row)[l] =
            make_uint2(pack_bf(accA[j].x), pack_bf(accA[j].y));
        reinterpret_cast<uint2*>(row + 64)[l] =
            make_uint2(pack_bf(accB[j].x), pack_bf(accB[j].y));
    }
}

// ---------------------------------------------------------------------------
// Kernel 2: reduce bf16 partials -> roi -> logits (warp-parallel dots).
// grid = 256 (block per proposal), block = 256.
// ---------------------------------------------------------------------------
__global__ __launch_bounds__(256)
void reduce_kernel(const float* __restrict__ W_cls, const float* __restrict__ b_cls,
                   const float* __restrict__ W_obj, const float* __restrict__ b_obj)
{
    const int p   = blockIdx.x;
    const int tid = threadIdx.x;
    const int w   = tid >> 5;
    const int l   = tid & 31;

    __shared__ float roi[RFEAT];
    __shared__ float sc[8];

    // Feature sums: thread t < 128 owns u32 column t (feats 2t, 2t+1).
    float e0 = 0.f, o0 = 0.f, e1 = 0.f, o1 = 0.f;
    if (tid < 128) {
        const uint32_t* colp = &g_partial_bf[0][p][tid];
        const size_t stride = (size_t)PPROP * (RFEAT / 2);
#pragma unroll
        for (int c = 0; c < NCHUNK; c += 2) {
            const uint32_t ua = colp[(size_t)c * stride];
            const uint32_t ub = colp[(size_t)(c + 1) * stride];
            e0 += __uint_as_float(ua << 16);
            o0 += __uint_as_float(ua & 0xFFFF0000u);
            e1 += __uint_as_float(ub << 16);
            o1 += __uint_as_float(ub & 0xFFFF0000u);
        }
    }

    // Count reduction
    float cv = (tid < NCHUNK) ? g_pcounts[tid][p] : 0.f;
#pragma unroll
    for (int o = 16; o > 0; o >>= 1) cv += __shfl_down_sync(0xffffffffu, cv, o);
    if (l == 0) sc[w] = cv;
    __syncthreads();
    if (tid == 0) {
        float t = 0.f;
#pragma unroll
        for (int i = 0; i < 8; i++) t += sc[i];
        sc[0] = 1.0f / fmaxf(t, 1.0f);
    }
    __syncthreads();
    if (tid < 128) {
        roi[2 * tid]     = (e0 + e1) * sc[0];
        roi[2 * tid + 1] = (o0 + o1) * sc[0];
    }
    __syncthreads();

    // Logits: 42 warp-reduced dot products of length 256
    for (int o = w; o < 2 * CO; o += 8) {
        const bool isobj = o >= CO;
        const int  j     = isobj ? o - CO : o;
        const float* Wm  = isobj ? W_obj : W_cls;
        float a = 0.f;
#pragma unroll
        for (int f = l; f < RFEAT; f += 32) a += roi[f] * Wm[f * CO + j];
#pragma unroll
        for (int off = 16; off > 0; off >>= 1)
            a += __shfl_xor_sync(0xffffffffu, a, off);
        if (l == 0)
            (isobj ? g_obj : g_cls)[p * CO + j] = a + (isobj ? b_obj[j] : b_cls[j]);
    }
}

// ---------------------------------------------------------------------------
// Kernel 3: softmaxes + product. 1 block, 1024 threads.
// ---------------------------------------------------------------------------
__global__ __launch_bounds__(1024)
void softmax_kernel(float* __restrict__ out)
{
    const int tid = threadIdx.x;
    __shared__ float sobj[PPROP * CO];   // 21 KB
    __shared__ float red[CO][48];
    __shared__ float cmax[CO], cinv[CO];

    for (int e = tid; e < PPROP * CO; e += 1024) sobj[e] = g_obj[e];
    __syncthreads();

    const int c = tid / 48;   // column (0..20) for tid < 1008
    const int r = tid % 48;

    if (tid < 1008) {
        float m = -3.4e38f;
        for (int p = r; p < PPROP; p += 48) m = fmaxf(m, sobj[p * CO + c]);
        red[c][r] = m;
    }
    __syncthreads();
    if (tid < CO) {
        float m = red[tid][0];
#pragma unroll
        for (int k = 1; k < 48; k++) m = fmaxf(m, red[tid][k]);
        cmax[tid] = m;
    }
    __syncthreads();
    if (tid < 1008) {
        const float m = cmax[c];
        float sm = 0.f;
        for (int p = r; p < PPROP; p += 48) {
            const float e = expf(sobj[p * CO + c] - m);
            sobj[p * CO + c] = e;
            sm += e;
        }
        red[c][r] = sm;
    }
    __syncthreads();
    if (tid < CO) {
        float sm = 0.f;
#pragma unroll
        for (int k = 0; k < 48; k++) sm += red[tid][k];
        cinv[tid] = 1.0f / sm;
    }
    __syncthreads();

    // cls row softmax (axis=1) + product; rows split 2 ways over 512 threads
    if (tid < 512) {
        const int row  = tid >> 1;
        const int half = tid & 1;
        float lg[CO];
        float m = -3.4e38f;
#pragma unroll
        for (int j = 0; j < CO; j++) { lg[j] = g_cls[row * CO + j]; m = fmaxf(m, lg[j]); }
        float sm = 0.f;
#pragma unroll
        for (int j = 0; j < CO; j++) { lg[j] = expf(lg[j] - m); sm += lg[j]; }
        const float invs = 1.0f / sm;
        if (half == 0) {
#pragma unroll
            for (int j = 0; j < 11; j++)
                out[row * CO + j] = lg[j] * invs * sobj[row * CO + j] * cinv[j];
        } else {
#pragma unroll
            for (int j = 11; j < CO; j++)
                out[row * CO + j] = lg[j] * invs * sobj[row * CO + j] * cinv[j];
        }
    }
}

// ---------------------------------------------------------------------------
extern "C" void kernel_launch(void* const* d_in, const int* in_sizes, int n_in,
                              void* d_out, int out_size)
{
    const float* proposals = (const float*)d_in[0];
    const float* input_xyz = (const float*)d_in[1];
    const float* seg_feats = (const float*)d_in[2];
    const float* W_cls     = (const float*)d_in[3];
    const float* b_cls     = (const float*)d_in[4];
    const float* W_obj     = (const float*)d_in[5];
    const float* b_obj     = (const float*)d_in[6];
    float* out = (float*)d_out;

    (void)in_sizes; (void)n_in; (void)out_size;

    cudaFuncSetAttribute(pool_kernel,
                         cudaFuncAttributeMaxDynamicSharedMemorySize,
                         POOL_SMEM_BYTES);
    pool_kernel<<<dim3(NCHUNK, 4), 512, POOL_SMEM_BYTES>>>(proposals, input_xyz, seg_feats);
    reduce_kernel<<<PPROP, 256>>>(W_cls, b_cls, W_obj, b_obj);
    softmax_kernel<<<1, 1024>>>(out);
}

// round 14
// speedup vs baseline: 1.0764x; 1.0510x over previous
#include <cuda_runtime.h>
#include <cstdint>

#define NPTS   100000
#define PPROP  256
#define RFEAT  256
#define CO     21
#define NCHUNK 74
#define CHUNK  1352      // 74*1352 = 100048 >= 100000
#define CPAD   1536
#define NWORD  48        // 48 u32 mask words (45 used: 15 stages x 3)
#define SPTS   96        // points per stage (3 mask words)
#define NSTAGE 15        // 15*96 = 1440 >= 1352
#define PG     128       // proposals per block

// Scratch (__device__ globals: allocation-free rule)
__device__ uint32_t g_partial_bf[NCHUNK][PPROP][RFEAT / 2];   // 9.7 MB bf16x2
__device__ float    g_pcounts[NCHUNK][PPROP];
__device__ float    g_cls[PPROP * CO];
__device__ float    g_obj[PPROP * CO];

__device__ __forceinline__ void cp16(uint32_t saddr, const void* gptr) {
    asm volatile("cp.async.cg.shared.global [%0], [%1], 16;\n"
                 :: "r"(saddr), "l"(gptr));
}
__device__ __forceinline__ void cp_commit() {
    asm volatile("cp.async.commit_group;\n");
}
__device__ __forceinline__ void cp_wait1() {
    asm volatile("cp.async.wait_group 1;\n");
}
#define ADD_F32X2(out, a, b) \
    asm("add.rn.f32x2 %0, %1, %2;" : "=l"(out) : "l"(a), "l"(b))

// pack f32x2 (lo = even feat, hi = odd feat) -> bf16x2 (lo16 = even feat)
static __device__ __forceinline__ uint32_t pack_bf(unsigned long long p) {
    uint32_t lo, hi, r;
    asm("mov.b64 {%0, %1}, %2;" : "=r"(lo), "=r"(hi) : "l"(p));
    asm("cvt.rn.bf16x2.f32 %0, %1, %2;" : "=r"(r)
        : "f"(__uint_as_float(hi)), "f"(__uint_as_float(lo)));
    return r;
}

struct PoolSmem {
    union {
        float4 sf[2][SPTS][64];   // 192 KB feature double-buffer (f32)
        float4 sxyz4[CPAD];       // 24 KB padded xyz (phase A only)
    } u;
    unsigned smaskT[NWORD][PG];   // 24 KB bitmaps, word-major
    int      sgrp[PG];            // slot -> original proposal id
    float    scnt[8][PG];
    float    scntTot[PG];
};
#define POOL_SMEM_BYTES ((int)sizeof(PoolSmem))

// ---------------------------------------------------------------------------
// Kernel 1: sparse ROI pooling, load-balanced.
// grid = (74 chunks, 2 proposal-groups of 128), block = 1024, 1 CTA/SM
// (exactly one wave of 148 CTAs). Feature HBM traffic halves vs PG=64.
// Phase A: stage chunk xyz as float4 -> full-chunk bitmaps per proposal;
//          exact per-proposal counts -> rank-sort 128 proposals by count ->
//          serpentine-assign 4 per warp (balances persistent box-volume skew)
//          -> repack bitmaps warp-grouped so the scan uses one LDS.128.
// Phase B: double-buffered cp.async stages of 96 pts x 256 f32 feats;
//          per stage each warp scans 3 mask words for its 4 slots
//          (amortizes per-stage Poisson imbalance 3x vs 32-pt tiles).
// Output: partial sums packed to bf16x2.
// ---------------------------------------------------------------------------
__global__ __launch_bounds__(1024, 1)
void pool_kernel(const float* __restrict__ proposals,
                 const float* __restrict__ xyz,
                 const float* __restrict__ feats)
{
    extern __shared__ char smem_raw[];
    PoolSmem* s = reinterpret_cast<PoolSmem*>(smem_raw);

    const int chunk = blockIdx.x;
    const int pbase = blockIdx.y * PG;
    const int tid   = threadIdx.x;
    const int w     = tid >> 5;
    const int l     = tid & 31;
    const int pm    = tid & 127;  // proposal this thread masks
    const int q     = tid >> 7;   // point range [192q, 192q+192)

    const int base = chunk * CHUNK;
    const int nPts = (NPTS - base < CHUNK) ? (NPTS - base) : CHUNK;

    // ---- Phase A: stage xyz as padded float4 (pad 2.0 -> outside all boxes)
    {
        const float* gx = xyz + (size_t)base * 3;
#pragma unroll
        for (int k = 0; k < 2; k++) {               // 2*1024 >= 1536
            const int j = tid + k * 1024;
            if (j < CPAD) {
                float x = 2.f, y = 2.f, z = 2.f;
                if (j < nPts) { x = gx[3*j]; y = gx[3*j+1]; z = gx[3*j+2]; }
                s->u.sxyz4[j] = make_float4(x, y, z, 0.f);
            }
        }
    }

    // Box bounds, bit-exact vs reference (no FMA contraction).
    float alox, ahix, aloy, ahiy, aloz, ahiz;
    {
        const float* pr = proposals + (size_t)(pbase + pm) * 6;
        const float cx = pr[0], cy = pr[1], cz = pr[2];
        const float hx = __fmul_rn(pr[3], 0.5f);
        const float hy = __fmul_rn(pr[4], 0.5f);
        const float hz = __fmul_rn(pr[5], 0.5f);
        alox = __fsub_rn(cx, hx);  ahix = __fadd_rn(cx, hx);
        aloy = __fsub_rn(cy, hy);  ahiy = __fadd_rn(cy, hy);
        aloz = __fsub_rn(cz, hz);  ahiz = __fadd_rn(cz, hz);
    }
    __syncthreads();

    // ---- Build masks: 6 words of 32 tests each (1 broadcast LDS.128/test)
    {
        float cnt = 0.f;
#pragma unroll
        for (int wd = 0; wd < 6; wd++) {
            unsigned bits = 0;
#pragma unroll
            for (int k = 0; k < 32; k++) {
                const float4 v = s->u.sxyz4[q * 192 + wd * 32 + k];
                const bool in = (v.x >= alox) & (v.x <= ahix) &
                                (v.y >= aloy) & (v.y <= ahiy) &
                                (v.z >= aloz) & (v.z <= ahiz);
                bits |= ((unsigned)in) << k;
            }
            s->smaskT[q * 6 + wd][pm] = bits;
            cnt += (float)__popc(bits);
        }
        s->scnt[q][pm] = cnt;
    }
    __syncthreads();

    // ---- Counts + balanced assignment ----
    if (tid < PG) {
        float c = 0.f;
#pragma unroll
        for (int k = 0; k < 8; k++) c += s->scnt[k][tid];
        s->scntTot[tid] = c;
        g_pcounts[chunk][pbase + tid] = c;
    }
    __syncthreads();
    if (tid < PG) {
        // rank by descending count (deterministic tie-break on index)
        const float mine = s->scntTot[tid];
        int rank = 0;
        for (int p = 0; p < PG; p++) {
            const float v = s->scntTot[p];
            rank += (v > mine) || ((v == mine) && (p < tid));
        }
        // serpentine: round r = rank>>5, pos = rank&31
        const int round = rank >> 5;
        const int pos   = rank & 31;
        const int wdst  = (round & 1) ? (31 - pos) : pos;
        s->sgrp[wdst * 4 + round] = tid;   // warp wdst, slot 'round' <- prop
    }
    __syncthreads();
    // ---- Repack bitmaps into slot order (in place via registers) ----
    {
        const int c  = tid & 127;   // target column (slot)
        const int qq = tid >> 7;
        const int src = s->sgrp[c];
        unsigned regs[6];
#pragma unroll
        for (int wd = 0; wd < 6; wd++) regs[wd] = s->smaskT[qq * 6 + wd][src];
        __syncthreads();
#pragma unroll
        for (int wd = 0; wd < 6; wd++) s->smaskT[qq * 6 + wd][c] = regs[wd];
    }
    __syncthreads();   // masks repacked; xyz area now reusable for features

    // ---- Phase B: double-buffered staged accumulation (96 pts/stage) ----
    ulonglong2 accA[4], accB[4];
#pragma unroll
    for (int j = 0; j < 4; j++) {
        accA[j].x = 0ull; accA[j].y = 0ull;
        accB[j].x = 0ull; accB[j].y = 0ull;
    }

    const float4* gf = reinterpret_cast<const float4*>(feats);

    const int ci = tid >> 6;   // base point within stage (0..15)
    const int cf = tid & 63;   // float4 column

    auto issue = [&](int st, int buf) {
        const int t0 = st * SPTS;
#pragma unroll
        for (int k = 0; k < 6; k++) {
            const int i = ci + 16 * k;
            const int pt = t0 + i;
            if (pt < nPts) {
                uint32_t sa = (uint32_t)__cvta_generic_to_shared(&s->u.sf[buf][i][cf]);
                cp16(sa, gf + (size_t)(base + pt) * 64 + cf);
            }
        }
        cp_commit();
    };

    issue(0, 0);
    for (int st = 0; st < NSTAGE; st++) {
        if (st + 1 < NSTAGE) issue(st + 1, (st + 1) & 1);
        else cp_commit();   // keep group count aligned
        cp_wait1();
        __syncthreads();    // stage st visible to all

        const int buf = st & 1;
#pragma unroll
        for (int wd3 = 0; wd3 < 3; wd3++) {
            const int word = 3 * st + wd3;
            const uint4 mw =
                *reinterpret_cast<const uint4*>(&s->smaskT[word][w << 2]);
            const int ibase = wd3 << 5;

#define SCAN_ONE(MWORD, J)                                                    \
            {                                                                 \
                unsigned m = (MWORD);                                         \
                while (m) {                                                   \
                    const int i = ibase + __ffs(m) - 1;                       \
                    m &= m - 1;                                               \
                    const ulonglong2 va =                                     \
                        *reinterpret_cast<const ulonglong2*>(&s->u.sf[buf][i][l]);      \
                    const ulonglong2 vb =                                     \
                        *reinterpret_cast<const ulonglong2*>(&s->u.sf[buf][i][l + 32]); \
                    ADD_F32X2(accA[J].x, accA[J].x, va.x);                    \
                    ADD_F32X2(accA[J].y, accA[J].y, va.y);                    \
                    ADD_F32X2(accB[J].x, accB[J].x, vb.x);                    \
                    ADD_F32X2(accB[J].y, accB[J].y, vb.y);                    \
                }                                                             \
            }
            SCAN_ONE(mw.x, 0)
            SCAN_ONE(mw.y, 1)
            SCAN_ONE(mw.z, 2)
            SCAN_ONE(mw.w, 3)
#undef SCAN_ONE
        }
        __syncthreads();    // stage consumed before buffer overwrite
    }

    // Write partial sums as bf16x2 (prop index via balanced assignment)
#pragma unroll
    for (int j = 0; j < 4; j++) {
        const int prop = s->sgrp[(w << 2) + j];
        uint32_t* row = &g_partial_bf[chunk][pbase + prop][0];
        reinterpret_cast<uint2*>(row)[l] =
            make_uint2(pack_bf(accA[j].x), pack_bf(accA[j].y));
        reinterpret_cast<uint2*>(row + 64)[l] =
            make_uint2(pack_bf(accB[j].x), pack_bf(accB[j].y));
    }
}

// ---------------------------------------------------------------------------
// Kernel 2: reduce bf16 partials -> roi -> logits (warp-parallel dots).
// grid = 256 (block per proposal), block = 256.
// ---------------------------------------------------------------------------
__global__ __launch_bounds__(256)
void reduce_kernel(const float* __restrict__ W_cls, const float* __restrict__ b_cls,
                   const float* __restrict__ W_obj, const float* __restrict__ b_obj)
{
    const int p   = blockIdx.x;
    const int tid = threadIdx.x;
    const int w   = tid >> 5;
    const int l   = tid & 31;

    __shared__ float roi[RFEAT];
    __shared__ float sc[8];

    float e0 = 0.f, o0 = 0.f, e1 = 0.f, o1 = 0.f;
    if (tid < 128) {
        const uint32_t* colp = &g_partial_bf[0][p][tid];
        const size_t stride = (size_t)PPROP * (RFEAT / 2);
#pragma unroll
        for (int c = 0; c < NCHUNK; c += 2) {
            const uint32_t ua = colp[(size_t)c * stride];
            const uint32_t ub = colp[(size_t)(c + 1) * stride];
            e0 += __uint_as_float(ua << 16);
            o0 += __uint_as_float(ua & 0xFFFF0000u);
            e1 += __uint_as_float(ub << 16);
            o1 += __uint_as_float(ub & 0xFFFF0000u);
        }
    }

    float cv = (tid < NCHUNK) ? g_pcounts[tid][p] : 0.f;
#pragma unroll
    for (int o = 16; o > 0; o >>= 1) cv += __shfl_down_sync(0xffffffffu, cv, o);
    if (l == 0) sc[w] = cv;
    __syncthreads();
    if (tid == 0) {
        float t = 0.f;
#pragma unroll
        for (int i = 0; i < 8; i++) t += sc[i];
        sc[0] = 1.0f / fmaxf(t, 1.0f);
    }
    __syncthreads();
    if (tid < 128) {
        roi[2 * tid]     = (e0 + e1) * sc[0];
        roi[2 * tid + 1] = (o0 + o1) * sc[0];
    }
    __syncthreads();

    for (int o = w; o < 2 * CO; o += 8) {
        const bool isobj = o >= CO;
        const int  j     = isobj ? o - CO : o;
        const float* Wm  = isobj ? W_obj : W_cls;
        float a = 0.f;
#pragma unroll
        for (int f = l; f < RFEAT; f += 32) a += roi[f] * Wm[f * CO + j];
#pragma unroll
        for (int off = 16; off > 0; off >>= 1)
            a += __shfl_xor_sync(0xffffffffu, a, off);
        if (l == 0)
            (isobj ? g_obj : g_cls)[p * CO + j] = a + (isobj ? b_obj[j] : b_cls[j]);
    }
}

// ---------------------------------------------------------------------------
// Kernel 3: softmaxes + product. 1 block, 1024 threads.
// ---------------------------------------------------------------------------
__global__ __launch_bounds__(1024)
void softmax_kernel(float* __restrict__ out)
{
    const int tid = threadIdx.x;
    __shared__ float sobj[PPROP * CO];   // 21 KB
    __shared__ float red[CO][48];
    __shared__ float cmax[CO], cinv[CO];

    for (int e = tid; e < PPROP * CO; e += 1024) sobj[e] = g_obj[e];
    __syncthreads();

    const int c = tid / 48;   // column (0..20) for tid < 1008
    const int r = tid % 48;

    if (tid < 1008) {
        float m = -3.4e38f;
        for (int p = r; p < PPROP; p += 48) m = fmaxf(m, sobj[p * CO + c]);
        red[c][r] = m;
    }
    __syncthreads();
    if (tid < CO) {
        float m = red[tid][0];
#pragma unroll
        for (int k = 1; k < 48; k++) m = fmaxf(m, red[tid][k]);
        cmax[tid] = m;
    }
    __syncthreads();
    if (tid < 1008) {
        const float m = cmax[c];
        float sm = 0.f;
        for (int p = r; p < PPROP; p += 48) {
            const float e = expf(sobj[p * CO + c] - m);
            sobj[p * CO + c] = e;
            sm += e;
        }
        red[c][r] = sm;
    }
    __syncthreads();
    if (tid < CO) {
        float sm = 0.f;
#pragma unroll
        for (int k = 0; k < 48; k++) sm += red[tid][k];
        cinv[tid] = 1.0f / sm;
    }
    __syncthreads();

    if (tid < 512) {
        const int row  = tid >> 1;
        const int half = tid & 1;
        float lg[CO];
        float m = -3.4e38f;
#pragma unroll
        for (int j = 0; j < CO; j++) { lg[j] = g_cls[row * CO + j]; m = fmaxf(m, lg[j]); }
        float sm = 0.f;
#pragma unroll
        for (int j = 0; j < CO; j++) { lg[j] = expf(lg[j] - m); sm += lg[j]; }
        const float invs = 1.0f / sm;
        if (half == 0) {
#pragma unroll
            for (int j = 0; j < 11; j++)
                out[row * CO + j] = lg[j] * invs * sobj[row * CO + j] * cinv[j];
        } else {
#pragma unroll
            for (int j = 11; j < CO; j++)
                out[row * CO + j] = lg[j] * invs * sobj[row * CO + j] * cinv[j];
        }
    }
}

// ---------------------------------------------------------------------------
extern "C" void kernel_launch(void* const* d_in, const int* in_sizes, int n_in,
                              void* d_out, int out_size)
{
    const float* proposals = (const float*)d_in[0];
    const float* input_xyz = (const float*)d_in[1];
    const float* seg_feats = (const float*)d_in[2];
    const float* W_cls     = (const float*)d_in[3];
    const float* b_cls     = (const float*)d_in[4];
    const float* W_obj     = (const float*)d_in[5];
    const float* b_obj     = (const float*)d_in[6];
    float* out = (float*)d_out;

    (void)in_sizes; (void)n_in; (void)out_size;

    cudaFuncSetAttribute(pool_kernel,
                         cudaFuncAttributeMaxDynamicSharedMemorySize,
                         POOL_SMEM_BYTES);
    pool_kernel<<<dim3(NCHUNK, 2), 1024, POOL_SMEM_BYTES>>>(proposals, input_xyz, seg_feats);
    reduce_kernel<<<PPROP, 256>>>(W_cls, b_cls, W_obj, b_obj);
    softmax_kernel<<<1, 1024>>>(out);
}

// round 15
// speedup vs baseline: 1.1347x; 1.0541x over previous
#include <cuda_runtime.h>
#include <cstdint>

#define NPTS   100000
#define PPROP  256
#define RFEAT  256
#define CO     21
#define NCHUNK 74
#define CHUNK  1352      // 74*1352 = 100048 >= 100000
#define CPAD   1536
#define NWORD  48        // mask words (45 used: 15 stages x 3)
#define SPTS   96        // points per stage (3 mask words)
#define NSTAGE 15        // 15*96 = 1440 >= 1352
#define PG     128       // proposals per block

// Scratch (__device__ globals: allocation-free rule)
__device__ uint32_t g_partial_bf[NCHUNK][PPROP][RFEAT / 2];   // 9.7 MB bf16x2
__device__ float    g_pcounts[NCHUNK][PPROP];
__device__ float    g_cls[PPROP * CO];
__device__ float    g_obj[PPROP * CO];

#define ADD_F32X2(out, a, b) \
    asm("add.rn.f32x2 %0, %1, %2;" : "=l"(out) : "l"(a), "l"(b))

// pack f32x2 (lo = even feat, hi = odd feat) -> bf16x2 (lo16 = even feat)
static __device__ __forceinline__ uint32_t pack_bf(unsigned long long p) {
    uint32_t lo, hi, r;
    asm("mov.b64 {%0, %1}, %2;" : "=r"(lo), "=r"(hi) : "l"(p));
    asm("cvt.rn.bf16x2.f32 %0, %1, %2;" : "=r"(r)
        : "f"(__uint_as_float(hi)), "f"(__uint_as_float(lo)));
    return r;
}

static __device__ __forceinline__ void mbar_init(uint32_t a, uint32_t c) {
    asm volatile("mbarrier.init.shared.b64 [%0], %1;" :: "r"(a), "r"(c) : "memory");
}
static __device__ __forceinline__ void mbar_expect_tx(uint32_t a, uint32_t bytes) {
    asm volatile("mbarrier.arrive.expect_tx.shared.b64 _, [%0], %1;"
                 :: "r"(a), "r"(bytes) : "memory");
}
static __device__ __forceinline__ void mbar_wait(uint32_t mbar, uint32_t parity) {
    uint32_t done;
    asm volatile("{\n\t.reg .pred p;\n\t"
                 "mbarrier.try_wait.parity.acquire.cta.shared::cta.b64 p, [%1], %2;\n\t"
                 "selp.b32 %0, 1, 0, p;\n\t}"
                 : "=r"(done) : "r"(mbar), "r"(parity) : "memory");
    if (!done) {
        asm volatile("{\n\t.reg .pred P1;\n\t"
                     "WL_%=:\n\t"
                     "mbarrier.try_wait.parity.acquire.cta.shared::cta.b64 P1, [%0], %1, 0x989680;\n\t"
                     "@P1 bra.uni WD_%=;\n\t"
                     "bra.uni WL_%=;\n\t"
                     "WD_%=:\n\t}" :: "r"(mbar), "r"(parity) : "memory");
    }
}
// One bulk DMA: contiguous GMEM -> SMEM, completion via mbarrier tx-bytes.
static __device__ __forceinline__ void bulk_copy(uint32_t dst_smem, const void* src,
                                                 uint32_t bytes, uint32_t mbar) {
    asm volatile("cp.async.bulk.shared::cluster.global.mbarrier::complete_tx::bytes "
                 "[%0], [%1], %2, [%3];"
                 :: "r"(dst_smem), "l"(src), "r"(bytes), "r"(mbar) : "memory");
}

struct PoolSmem {
    union {
        float4 sf[2][SPTS][64];   // 192 KB feature double-buffer (f32)
        float4 sxyz4[CPAD];       // 24 KB padded xyz (phase A only)
    } u;
    unsigned smaskT[NWORD][PG];   // 24 KB bitmaps, word-major
    int      sgrp[PG];
    float    scnt[8][PG];
    float    scntTot[PG];
    unsigned long long mbar[2];
};
#define POOL_SMEM_BYTES ((int)sizeof(PoolSmem))

// ---------------------------------------------------------------------------
// Kernel 1: sparse ROI pooling, bulk-DMA staged + load-balanced.
// grid = (74 chunks, 2 groups of 128 props), block = 1024, 1 CTA/SM.
// Phase A: xyz -> bitmaps; exact counts -> rank-sort -> serpentine warp
//          assignment (4 props/warp) -> repack bitmaps warp-grouped.
// Phase B: double-buffered stages of 96 pts x 1KB features staged by ONE
//          cp.async.bulk per stage (UBLKCP; kills the LDGSTS issue floor
//          that bound R6-R14), completion via mbarrier complete_tx.
// Output: partial sums packed bf16x2.
// ---------------------------------------------------------------------------
__global__ __launch_bounds__(1024, 1)
void pool_kernel(const float* __restrict__ proposals,
                 const float* __restrict__ xyz,
                 const float* __restrict__ feats)
{
    extern __shared__ char smem_raw[];
    PoolSmem* s = reinterpret_cast<PoolSmem*>(smem_raw);

    const int chunk = blockIdx.x;
    const int pbase = blockIdx.y * PG;
    const int tid   = threadIdx.x;
    const int w     = tid >> 5;
    const int l     = tid & 31;
    const int pm    = tid & 127;  // proposal this thread masks
    const int q     = tid >> 7;   // point range [192q, 192q+192)

    const int base = chunk * CHUNK;
    const int nPts = (NPTS - base < CHUNK) ? (NPTS - base) : CHUNK;

    const uint32_t mb0 = (uint32_t)__cvta_generic_to_shared(&s->mbar[0]);
    const uint32_t mb1 = (uint32_t)__cvta_generic_to_shared(&s->mbar[1]);
    if (tid == 0) { mbar_init(mb0, 1); mbar_init(mb1, 1); }

    // ---- Phase A: stage xyz as padded float4 (pad 2.0 -> outside all boxes)
    {
        const float* gx = xyz + (size_t)base * 3;
#pragma unroll
        for (int k = 0; k < 2; k++) {
            const int j = tid + k * 1024;
            if (j < CPAD) {
                float x = 2.f, y = 2.f, z = 2.f;
                if (j < nPts) { x = gx[3*j]; y = gx[3*j+1]; z = gx[3*j+2]; }
                s->u.sxyz4[j] = make_float4(x, y, z, 0.f);
            }
        }
    }

    // Box bounds, bit-exact vs reference (no FMA contraction).
    float alox, ahix, aloy, ahiy, aloz, ahiz;
    {
        const float* pr = proposals + (size_t)(pbase + pm) * 6;
        const float cx = pr[0], cy = pr[1], cz = pr[2];
        const float hx = __fmul_rn(pr[3], 0.5f);
        const float hy = __fmul_rn(pr[4], 0.5f);
        const float hz = __fmul_rn(pr[5], 0.5f);
        alox = __fsub_rn(cx, hx);  ahix = __fadd_rn(cx, hx);
        aloy = __fsub_rn(cy, hy);  ahiy = __fadd_rn(cy, hy);
        aloz = __fsub_rn(cz, hz);  ahiz = __fadd_rn(cz, hz);
    }
    __syncthreads();   // xyz + mbar init visible

    // ---- Build masks: 6 words of 32 tests each (1 broadcast LDS.128/test)
    {
        float cnt = 0.f;
#pragma unroll
        for (int wd = 0; wd < 6; wd++) {
            unsigned bits = 0;
#pragma unroll
            for (int k = 0; k < 32; k++) {
                const float4 v = s->u.sxyz4[q * 192 + wd * 32 + k];
                const bool in = (v.x >= alox) & (v.x <= ahix) &
                                (v.y >= aloy) & (v.y <= ahiy) &
                                (v.z >= aloz) & (v.z <= ahiz);
                bits |= ((unsigned)in) << k;
            }
            s->smaskT[q * 6 + wd][pm] = bits;
            cnt += (float)__popc(bits);
        }
        s->scnt[q][pm] = cnt;
    }
    __syncthreads();

    // ---- Counts + balanced assignment ----
    if (tid < PG) {
        float c = 0.f;
#pragma unroll
        for (int k = 0; k < 8; k++) c += s->scnt[k][tid];
        s->scntTot[tid] = c;
        g_pcounts[chunk][pbase + tid] = c;
    }
    __syncthreads();
    if (tid < PG) {
        const float mine = s->scntTot[tid];
        int rank = 0;
        for (int p = 0; p < PG; p++) {
            const float v = s->scntTot[p];
            rank += (v > mine) || ((v == mine) && (p < tid));
        }
        const int round = rank >> 5;
        const int pos   = rank & 31;
        const int wdst  = (round & 1) ? (31 - pos) : pos;
        s->sgrp[wdst * 4 + round] = tid;
    }
    __syncthreads();
    // ---- Repack bitmaps into slot order ----
    {
        const int c  = tid & 127;
        const int qq = tid >> 7;
        const int src = s->sgrp[c];
        unsigned regs[6];
#pragma unroll
        for (int wd = 0; wd < 6; wd++) regs[wd] = s->smaskT[qq * 6 + wd][src];
        __syncthreads();
#pragma unroll
        for (int wd = 0; wd < 6; wd++) s->smaskT[qq * 6 + wd][c] = regs[wd];
    }
    __syncthreads();   // masks repacked; xyz area now reusable for features

    // ---- Phase B: bulk-DMA double-buffered accumulation ----
    ulonglong2 accA[4], accB[4];
#pragma unroll
    for (int j = 0; j < 4; j++) {
        accA[j].x = 0ull; accA[j].y = 0ull;
        accB[j].x = 0ull; accB[j].y = 0ull;
    }

    // one bulk copy per stage: rows are contiguous 1KB feature rows
    auto issue = [&](int st, uint32_t mb, uint32_t dst) {
        const int t0 = st * SPTS;
        int rows = nPts - t0;
        if (rows > SPTS) rows = SPTS;
        const uint32_t bytes = (rows > 0) ? (uint32_t)rows * 1024u : 0u;
        mbar_expect_tx(mb, bytes);
        if (bytes)
            bulk_copy(dst, feats + (size_t)(base + t0) * RFEAT, bytes, mb);
    };

    const uint32_t sf0 = (uint32_t)__cvta_generic_to_shared(&s->u.sf[0][0][0]);
    const uint32_t sf1 = (uint32_t)__cvta_generic_to_shared(&s->u.sf[1][0][0]);

    if (tid == 0) { issue(0, mb0, sf0); issue(1, mb1, sf1); }

    int ph0 = 0, ph1 = 0;
    for (int st = 0; st < NSTAGE; st++) {
        const int b = st & 1;
        if (b == 0) { mbar_wait(mb0, ph0); ph0 ^= 1; }
        else        { mbar_wait(mb1, ph1); ph1 ^= 1; }

#pragma unroll
        for (int wd3 = 0; wd3 < 3; wd3++) {
            const int word = 3 * st + wd3;
            const uint4 mw =
                *reinterpret_cast<const uint4*>(&s->smaskT[word][w << 2]);
            const int ibase = wd3 << 5;

#define SCAN_ONE(MWORD, J)                                                    \
            {                                                                 \
                unsigned m = (MWORD);                                         \
                while (m) {                                                   \
                    const int i = ibase + __ffs(m) - 1;                       \
                    m &= m - 1;                                               \
                    const ulonglong2 va =                                     \
                        *reinterpret_cast<const ulonglong2*>(&s->u.sf[b][i][l]);      \
                    const ulonglong2 vb =                                     \
                        *reinterpret_cast<const ulonglong2*>(&s->u.sf[b][i][l + 32]); \
                    ADD_F32X2(accA[J].x, accA[J].x, va.x);                    \
                    ADD_F32X2(accA[J].y, accA[J].y, va.y);                    \
                    ADD_F32X2(accB[J].x, accB[J].x, vb.x);                    \
                    ADD_F32X2(accB[J].y, accB[J].y, vb.y);                    \
                }                                                             \
            }
            SCAN_ONE(mw.x, 0)
            SCAN_ONE(mw.y, 1)
            SCAN_ONE(mw.z, 2)
            SCAN_ONE(mw.w, 3)
#undef SCAN_ONE
        }
        __syncthreads();   // stage fully consumed by all warps

        if (tid == 0 && st + 2 < NSTAGE)
            issue(st + 2, b == 0 ? mb0 : mb1, b == 0 ? sf0 : sf1);
    }

    // Write partial sums as bf16x2 (prop index via balanced assignment)
#pragma unroll
    for (int j = 0; j < 4; j++) {
        const int prop = s->sgrp[(w << 2) + j];
        uint32_t* row = &g_partial_bf[chunk][pbase + prop][0];
        reinterpret_cast<uint2*>(row)[l] =
            make_uint2(pack_bf(accA[j].x), pack_bf(accA[j].y));
        reinterpret_cast<uint2*>(row + 64)[l] =
            make_uint2(pack_bf(accB[j].x), pack_bf(accB[j].y));
    }
}

// ---------------------------------------------------------------------------
// Kernel 2: reduce bf16 partials -> roi -> logits (warp-parallel dots).
// grid = 256 (block per proposal), block = 256.
// ---------------------------------------------------------------------------
__global__ __launch_bounds__(256)
void reduce_kernel(const float* __restrict__ W_cls, const float* __restrict__ b_cls,
                   const float* __restrict__ W_obj, const float* __restrict__ b_obj)
{
    const int p   = blockIdx.x;
    const int tid = threadIdx.x;
    const int w   = tid >> 5;
    const int l   = tid & 31;

    __shared__ float roi[RFEAT];
    __shared__ float sc[8];

    float e0 = 0.f, o0 = 0.f, e1 = 0.f, o1 = 0.f;
    if (tid < 128) {
        const uint32_t* colp = &g_partial_bf[0][p][tid];
        const size_t stride = (size_t)PPROP * (RFEAT / 2);
#pragma unroll
        for (int c = 0; c < NCHUNK; c += 2) {
            const uint32_t ua = colp[(size_t)c * stride];
            const uint32_t ub = colp[(size_t)(c + 1) * stride];
            e0 += __uint_as_float(ua << 16);
            o0 += __uint_as_float(ua & 0xFFFF0000u);
            e1 += __uint_as_float(ub << 16);
            o1 += __uint_as_float(ub & 0xFFFF0000u);
        }
    }

    float cv = (tid < NCHUNK) ? g_pcounts[tid][p] : 0.f;
#pragma unroll
    for (int o = 16; o > 0; o >>= 1) cv += __shfl_down_sync(0xffffffffu, cv, o);
    if (l == 0) sc[w] = cv;
    __syncthreads();
    if (tid == 0) {
        float t = 0.f;
#pragma unroll
        for (int i = 0; i < 8; i++) t += sc[i];
        sc[0] = 1.0f / fmaxf(t, 1.0f);
    }
    __syncthreads();
    if (tid < 128) {
        roi[2 * tid]     = (e0 + e1) * sc[0];
        roi[2 * tid + 1] = (o0 + o1) * sc[0];
    }
    __syncthreads();

    for (int o = w; o < 2 * CO; o += 8) {
        const bool isobj = o >= CO;
        const int  j     = isobj ? o - CO : o;
        const float* Wm  = isobj ? W_obj : W_cls;
        float a = 0.f;
#pragma unroll
        for (int f = l; f < RFEAT; f += 32) a += roi[f] * Wm[f * CO + j];
#pragma unroll
        for (int off = 16; off > 0; off >>= 1)
            a += __shfl_xor_sync(0xffffffffu, a, off);
        if (l == 0)
            (isobj ? g_obj : g_cls)[p * CO + j] = a + (isobj ? b_obj[j] : b_cls[j]);
    }
}

// ---------------------------------------------------------------------------
// Kernel 3: softmaxes + product. 1 block, 1024 threads.
// ---------------------------------------------------------------------------
__global__ __launch_bounds__(1024)
void softmax_kernel(float* __restrict__ out)
{
    const int tid = threadIdx.x;
    __shared__ float sobj[PPROP * CO];
    __shared__ float red[CO][48];
    __shared__ float cmax[CO], cinv[CO];

    for (int e = tid; e < PPROP * CO; e += 1024) sobj[e] = g_obj[e];
    __syncthreads();

    const int c = tid / 48;
    const int r = tid % 48;

    if (tid < 1008) {
        float m = -3.4e38f;
        for (int p = r; p < PPROP; p += 48) m = fmaxf(m, sobj[p * CO + c]);
        red[c][r] = m;
    }
    __syncthreads();
    if (tid < CO) {
        float m = red[tid][0];
#pragma unroll
        for (int k = 1; k < 48; k++) m = fmaxf(m, red[tid][k]);
        cmax[tid] = m;
    }
    __syncthreads();
    if (tid < 1008) {
        const float m = cmax[c];
        float sm = 0.f;
        for (int p = r; p < PPROP; p += 48) {
            const float e = expf(sobj[p * CO + c] - m);
            sobj[p * CO + c] = e;
            sm += e;
        }
        red[c][r] = sm;
    }
    __syncthreads();
    if (tid < CO) {
        float sm = 0.f;
#pragma unroll
        for (int k = 0; k < 48; k++) sm += red[tid][k];
        cinv[tid] = 1.0f / sm;
    }
    __syncthreads();

    if (tid < 512) {
        const int row  = tid >> 1;
        const int half = tid & 1;
        float lg[CO];
        float m = -3.4e38f;
#pragma unroll
        for (int j = 0; j < CO; j++) { lg[j] = g_cls[row * CO + j]; m = fmaxf(m, lg[j]); }
        float sm = 0.f;
#pragma unroll
        for (int j = 0; j < CO; j++) { lg[j] = expf(lg[j] - m); sm += lg[j]; }
        const float invs = 1.0f / sm;
        if (half == 0) {
#pragma unroll
            for (int j = 0; j < 11; j++)
                out[row * CO + j] = lg[j] * invs * sobj[row * CO + j] * cinv[j];
        } else {
#pragma unroll
            for (int j = 11; j < CO; j++)
                out[row * CO + j] = lg[j] * invs * sobj[row * CO + j] * cinv[j];
        }
    }
}

// ---------------------------------------------------------------------------
extern "C" void kernel_launch(void* const* d_in, const int* in_sizes, int n_in,
                              void* d_out, int out_size)
{
    const float* proposals = (const float*)d_in[0];
    const float* input_xyz = (const float*)d_in[1];
    const float* seg_feats = (const float*)d_in[2];
    const float* W_cls     = (const float*)d_in[3];
    const float* b_cls     = (const float*)d_in[4];
    const float* W_obj     = (const float*)d_in[5];
    const float* b_obj     = (const float*)d_in[6];
    float* out = (float*)d_out;

    (void)in_sizes; (void)n_in; (void)out_size;

    cudaFuncSetAttribute(pool_kernel,
                         cudaFuncAttributeMaxDynamicSharedMemorySize,
                         POOL_SMEM_BYTES);
    pool_kernel<<<dim3(NCHUNK, 2), 1024, POOL_SMEM_BYTES>>>(proposals, input_xyz, seg_feats);
    reduce_kernel<<<PPROP, 256>>>(W_cls, b_cls, W_obj, b_obj);
    softmax_kernel<<<1, 1024>>>(out);
}